// round 13
// baseline (speedup 1.0000x reference)
#include <cuda_runtime.h>
#include <cuda_fp16.h>
#include <cstdint>

#define D_MODEL 1024
#define NE 64
#define NN 128
#define TROWS 32            // rows per tile
#define BK 64               // fp32 K per chunk
#define NCH 16
#define CSTRIDE 132         // 528B rows: 16B-aligned for every row (do NOT shrink)
#define SM_B 16384          // B base (A: [2buf][2split][4KB] = 16KB @0)
#define SM_C 81920          // C base (B: [2buf][2split][16KB] = 64KB)
#define SMEM_BYTES (SM_C + TROWS * CSTRIDE * 4)   // 98816

// pre-split fp16 weights, pre-swizzled [split][chunk] 16KB images
__device__ __align__(128) unsigned char g_Bf[2 * NCH * 16384];

#define SWZB(r, c) ((r) * 256 + ((c) ^ (((r) & 7) << 4)))

__device__ __forceinline__ uint32_t smem_u32(const void* p) {
    uint32_t a;
    asm("{ .reg .u64 t; cvta.to.shared.u64 t, %1; cvt.u32.u64 %0, t; }" : "=r"(a) : "l"(p));
    return a;
}
#define CP16(dst, src) asm volatile("cp.async.ca.shared.global [%0], [%1], 16;" :: "r"(dst), "l"(src))
#define CP_COMMIT()    asm volatile("cp.async.commit_group;")
#define CP_WAIT0()     asm volatile("cp.async.wait_group 0;")

#define LDSM4(r, p) \
    asm volatile("ldmatrix.sync.aligned.m8n8.x4.shared.b16 {%0,%1,%2,%3}, [%4];" \
                 : "=r"((r)[0]), "=r"((r)[1]), "=r"((r)[2]), "=r"((r)[3]) : "r"(p))
#define LDSM4T(r, p) \
    asm volatile("ldmatrix.sync.aligned.m8n8.x4.trans.shared.b16 {%0,%1,%2,%3}, [%4];" \
                 : "=r"((r)[0]), "=r"((r)[1]), "=r"((r)[2]), "=r"((r)[3]) : "r"(p))
#define MMA16816(d, a, b0, b1) \
    asm volatile("mma.sync.aligned.m16n8k16.row.col.f32.f16.f16.f32 " \
                 "{%0,%1,%2,%3}, {%4,%5,%6,%7}, {%8,%9}, {%0,%1,%2,%3};" \
                 : "+f"((d)[0]), "+f"((d)[1]), "+f"((d)[2]), "+f"((d)[3]) \
                 : "r"((a)[0]), "r"((a)[1]), "r"((a)[2]), "r"((a)[3]), "r"(b0), "r"(b1))

// ============================================================
// Prep: fp16 2-split of W_route||W_noise into swizzled k-chunk images
// ============================================================
__global__ void prep_w(const float* __restrict__ Wr, const float* __restrict__ Wn) {
    int idx = blockIdx.x * blockDim.x + threadIdx.x;
    int k = idx >> 6;
    int n = (idx & 63) * 2;
    float x = (n < NE) ? Wr[n * D_MODEL + k] : Wn[(n - NE) * D_MODEL + k];
    float y = (n + 1 < NE) ? Wr[(n + 1) * D_MODEL + k] : Wn[(n + 1 - NE) * D_MODEL + k];
    __half2 h0 = __floats2half2_rn(x, y);
    float2 f0 = __half22float2(h0);
    __half2 h1 = __floats2half2_rn(x - f0.x, y - f0.y);
    int c = k >> 6, kr = k & 63;
    uint32_t off = SWZB(kr, n * 2);
    *(uint32_t*)(g_Bf + ((size_t)c << 14) + off) = reinterpret_cast<uint32_t&>(h0);
    *(uint32_t*)(g_Bf + (((size_t)(NCH + c)) << 14) + off) = reinterpret_cast<uint32_t&>(h1);
}

__device__ __forceinline__ void split_pack8(float4 a, float4 b, uint4& s0, uint4& s1) {
    __half2 p0 = __floats2half2_rn(a.x, a.y);
    __half2 p1 = __floats2half2_rn(a.z, a.w);
    __half2 p2 = __floats2half2_rn(b.x, b.y);
    __half2 p3 = __floats2half2_rn(b.z, b.w);
    float2 f0 = __half22float2(p0), f1 = __half22float2(p1);
    float2 f2 = __half22float2(p2), f3 = __half22float2(p3);
    __half2 q0 = __floats2half2_rn(a.x - f0.x, a.y - f0.y);
    __half2 q1 = __floats2half2_rn(a.z - f1.x, a.w - f1.y);
    __half2 q2 = __floats2half2_rn(b.x - f2.x, b.y - f2.y);
    __half2 q3 = __floats2half2_rn(b.z - f3.x, b.w - f3.y);
    s0.x = reinterpret_cast<uint32_t&>(p0); s0.y = reinterpret_cast<uint32_t&>(p1);
    s0.z = reinterpret_cast<uint32_t&>(p2); s0.w = reinterpret_cast<uint32_t&>(p3);
    s1.x = reinterpret_cast<uint32_t&>(q0); s1.y = reinterpret_cast<uint32_t&>(q1);
    s1.z = reinterpret_cast<uint32_t&>(q2); s1.w = reinterpret_cast<uint32_t&>(q3);
}

// ============================================================
// Persistent balanced split-fp16 HMMA GEMM + fused router epilogue
// 296 CTAs, 2/SM; 32-row tiles, variable count per CTA; warp tile 16x32
// ============================================================
__global__ void __launch_bounds__(256, 2)
moe_mma(const float* __restrict__ A, const float* __restrict__ noise,
        const float* __restrict__ br, const float* __restrict__ bn,
        float* __restrict__ out, int M, int write_idx) {
    extern __shared__ __align__(128) unsigned char smem[];
    __shared__ float bias[NN];
    const uint32_t sb = smem_u32(smem);
    const int tid = threadIdx.x;
    const int w = tid >> 5, l = tid & 31;
    const int bid = blockIdx.x;

    if (tid < NN) bias[tid] = (tid < NE) ? br[tid] : bn[tid - NE];

    // ---- balanced static schedule: tiles of 32 rows ----
    const int tiles = M / TROWS;                 // 1024
    const int qa = (tiles + 295) / 296;          // 4
    int t0, ntl;
    if (bid < 148) { ntl = qa; t0 = bid * qa; }
    else {
        int r = bid - 148;
        int rem = tiles - 148 * qa;              // 432
        int qb = rem / 148;                      // 2
        int n3 = rem - qb * 148;                 // 136
        if (r < n3) { ntl = qb + 1; t0 = 148 * qa + r * (qb + 1); }
        else        { ntl = qb;     t0 = 148 * qa + n3 * (qb + 1) + (r - n3) * qb; }
    }
    const int gend = ntl * NCH;

    const int wm = (w & 1) * 16;          // 2 row groups x 16
    const int n0 = (w >> 1) * 32;         // 4 col groups x 32

    const int l16 = l & 15;
    const uint32_t khalf16 = (uint32_t)((l >> 4) << 4);
    const uint32_t Ra  = (uint32_t)(wm + l16) * 128;
    const uint32_t rxa = ((uint32_t)(l16 & 7)) << 4;
    const uint32_t Rb0 = (uint32_t)l16 * 256;
    const uint32_t rxb = ((uint32_t)(l16 & 7)) << 4;
    const uint32_t cbb = (uint32_t)(n0 * 2) + khalf16;

    // A loader: 32 rows, 8 threads/row, 8 floats each
    const int arow = tid >> 3, aq = tid & 7;
    const float* abase = A + (size_t)arow * D_MODEL + aq * 8;
    const uint32_t a_phys = (uint32_t)arow * 128 + (((uint32_t)(aq * 16)) ^ (((uint32_t)(arow & 7)) << 4));

    float acc[4][4];
#pragma unroll
    for (int j = 0; j < 4; j++)
#pragma unroll
        for (int q = 0; q < 4; q++) acc[j][q] = 0.f;

    float4 av[2];
    auto ldg_a = [&](int g) {
        int tt = t0 + (g >> 4), c = g & 15;
        const float* p = abase + (size_t)tt * TROWS * D_MODEL + c * BK;
        av[0] = *(const float4*)(p);
        av[1] = *(const float4*)(p + 4);
    };
    auto cp_b = [&](int c, int buf) {
#pragma unroll
        for (int s = 0; s < 2; s++) {
            const unsigned char* src = g_Bf + (((size_t)(s * NCH + c)) << 14);
            uint32_t dst = sb + SM_B + buf * 32768 + s * 16384;
#pragma unroll
            for (int j = 0; j < 4; j++) {
                uint32_t o = (uint32_t)(tid + j * 256) * 16;
                CP16(dst + o, src + o);
            }
        }
        CP_COMMIT();
    };
    auto sts_a = [&](int buf) {
        unsigned char* b0 = smem + buf * 8192;
        uint4 s0, s1;
        split_pack8(av[0], av[1], s0, s1);
        *(uint4*)(b0 + a_phys) = s0;
        *(uint4*)(b0 + 4096 + a_phys) = s1;
    };

    // ---- prologue ----
    ldg_a(0);
    cp_b(0, 0);
    sts_a(0);
    CP_WAIT0();
    __syncthreads();

    float* C = (float*)(smem + SM_C);

    for (int g = 0; g < gend; g++) {
        int c = g & 15, buf = g & 1;
        if (g + 1 < gend) { ldg_a(g + 1); cp_b((g + 1) & 15, buf ^ 1); }

        uint32_t Ab = sb + buf * 8192;
        uint32_t Bb = sb + SM_B + buf * 32768;
#pragma unroll
        for (int ks = 0; ks < 4; ks++) {
            uint32_t ca = ((uint32_t)(ks * 32) + khalf16) ^ rxa;
            uint32_t a0f[4], a1f[4];
            LDSM4(a0f, Ab + Ra + ca);
            LDSM4(a1f, Ab + 4096 + Ra + ca);

            uint32_t Rb = Rb0 + (uint32_t)ks * 4096;
            uint32_t b0f[2][4], b1f[2][4];
#pragma unroll
            for (int nt = 0; nt < 2; nt++) {
                uint32_t cc = (cbb + (uint32_t)(nt * 32)) ^ rxb;
                LDSM4T(b0f[nt], Bb + Rb + cc);
                LDSM4T(b1f[nt], Bb + 16384 + Rb + cc);
            }
#pragma unroll
            for (int nt = 0; nt < 2; nt++) {
                MMA16816(acc[2 * nt],     a0f, b0f[nt][0], b0f[nt][1]);
                MMA16816(acc[2 * nt + 1], a0f, b0f[nt][2], b0f[nt][3]);
            }
#pragma unroll
            for (int nt = 0; nt < 2; nt++) {
                MMA16816(acc[2 * nt],     a0f, b1f[nt][0], b1f[nt][1]);
                MMA16816(acc[2 * nt + 1], a0f, b1f[nt][2], b1f[nt][3]);
            }
#pragma unroll
            for (int nt = 0; nt < 2; nt++) {
                MMA16816(acc[2 * nt],     a1f, b0f[nt][0], b0f[nt][1]);
                MMA16816(acc[2 * nt + 1], a1f, b0f[nt][2], b0f[nt][3]);
            }
        }

        if (c == 15) {
            // tile finished: accs -> C, reset
            int r0 = wm + (l >> 2);
            int cb = n0 + (l & 3) * 2;
#pragma unroll
            for (int nt = 0; nt < 4; nt++) {
                int cc = cb + nt * 8;
                *(float2*)(C + r0 * CSTRIDE + cc)       = *(float2*)&acc[nt][0];
                *(float2*)(C + (r0 + 8) * CSTRIDE + cc) = *(float2*)&acc[nt][2];
                acc[nt][0] = acc[nt][1] = acc[nt][2] = acc[nt][3] = 0.f;
            }
        }

        if (g + 1 < gend) { sts_a(buf ^ 1); CP_WAIT0(); }
        __syncthreads();

        if (c == 15) {
            // ---- router epilogue: 8 warps x 4 rows; 8 lanes per row ----
            const int m0 = (t0 + (g >> 4)) * TROWS;
            const int row = (w << 2) + (l >> 3);
            const int grp = l & 7;
            const int e0 = grp * 8;
            const int token = m0 + row;
            const float* crow = C + row * CSTRIDE;

            float4 r_a = *(const float4*)(crow + e0);
            float4 r_b = *(const float4*)(crow + e0 + 4);
            float4 n_a = *(const float4*)(crow + NE + e0);
            float4 n_b = *(const float4*)(crow + NE + e0 + 4);
            const float* nrow = noise + (size_t)token * NE + e0;
            float4 z_a = *(const float4*)(nrow);
            float4 z_b = *(const float4*)(nrow + 4);

            float rl[8] = {r_a.x, r_a.y, r_a.z, r_a.w, r_b.x, r_b.y, r_b.z, r_b.w};
            float nl[8] = {n_a.x, n_a.y, n_a.z, n_a.w, n_b.x, n_b.y, n_b.z, n_b.w};
            float nz[8] = {z_a.x, z_a.y, z_a.z, z_a.w, z_b.x, z_b.y, z_b.z, z_b.w};

            float v1 = -1e30f, v2 = -1e30f;
            int i1 = 0, i2 = 0;
#pragma unroll
            for (int e = 0; e < 8; e++) {
                float nlg = nl[e] + bias[NE + e0 + e];
                float sp  = fmaxf(nlg, 0.f) + log1pf(expf(-fabsf(nlg)));
                float z   = rl[e] + bias[e0 + e] + nz[e] * sp;
                if (z > v1)      { v2 = v1; i2 = i1; v1 = z; i1 = e0 + e; }
                else if (z > v2) { v2 = z; i2 = e0 + e; }
            }
            // butterfly merge across the 8 lanes of this row group
#pragma unroll
            for (int off = 4; off > 0; off >>= 1) {
                float w1 = __shfl_xor_sync(0xffffffffu, v1, off);
                int   j1 = __shfl_xor_sync(0xffffffffu, i1, off);
                float w2 = __shfl_xor_sync(0xffffffffu, v2, off);
                int   j2 = __shfl_xor_sync(0xffffffffu, i2, off);
                bool bwins = (w1 > v1) || (w1 == v1 && j1 < i1);
                if (bwins) {
                    float c2v; int c2i;
                    if ((v1 > w2) || (v1 == w2 && i1 < j2)) { c2v = v1; c2i = i1; }
                    else                                    { c2v = w2; c2i = j2; }
                    v1 = w1; i1 = j1; v2 = c2v; i2 = c2i;
                } else {
                    if ((w1 > v2) || (w1 == v2 && j1 < i2)) { v2 = w1; i2 = j1; }
                }
            }

            float ex  = expf(v2 - v1);
            float inv = 1.f / (1.f + ex);
            float p1 = inv, p2 = ex * inv;

            float* orow = out + (size_t)token * NE + e0;
            float o[8];
#pragma unroll
            for (int e = 0; e < 8; e++) {
                int ge = e0 + e;
                o[e] = (ge == i1) ? p1 : ((ge == i2) ? p2 : 0.f);
            }
            *(float4*)(orow)     = *(float4*)&o[0];
            *(float4*)(orow + 4) = *(float4*)&o[4];

            if (write_idx && grp == 0) {
                float2 iv = make_float2((float)i1, (float)i2);
                *(float2*)(out + (size_t)M * NE + (size_t)token * 2) = iv;
            }
        }
    }
}

// ============================================================
extern "C" void kernel_launch(void* const* d_in, const int* in_sizes, int n_in,
                              void* d_out, int out_size) {
    const float* mh    = (const float*)d_in[0];
    const float* noise = (const float*)d_in[1];
    const float* Wr    = (const float*)d_in[2];
    const float* br    = (const float*)d_in[3];
    const float* Wn    = (const float*)d_in[4];
    const float* bn    = (const float*)d_in[5];
    float* out = (float*)d_out;

    int M = in_sizes[0] / D_MODEL;   // 32768

    cudaFuncSetAttribute(moe_mma, cudaFuncAttributeMaxDynamicSharedMemorySize, SMEM_BYTES);

    prep_w<<<(D_MODEL * NN / 2) / 256, 256>>>(Wr, Wn);

    int write_idx = (out_size >= M * NE + M * 2) ? 1 : 0;
    moe_mma<<<296, 256, SMEM_BYTES>>>(mh, noise, br, bn, out, M, write_idx);
}